// round 1
// baseline (speedup 1.0000x reference)
#include <cuda_runtime.h>
#include <math_constants.h>

#define Bc 2
#define Tc 2048
#define Dc 1024
#define Hc 16
#define HDc 64
#define Mc (Bc*Tc)

// Scratch (device globals; no runtime allocation)
__device__ __align__(16) float g_q[Bc*Hc*Tc*HDc];     // (b,h,t,hd)
__device__ __align__(16) float g_k[Bc*Hc*HDc*Tc];     // (b,h,hd,t)  TRANSPOSED
__device__ __align__(16) float g_v[Bc*Hc*Tc*HDc];     // (b,h,t,hd)
__device__ __align__(16) float g_o[Bc*Tc*Dc];         // (b,t,d)
__device__ __align__(16) float g_ksum[Bc*Hc*HDc];
__device__ __align__(16) float g_gdiag[Hc*HDc];

// ---------------------------------------------------------------------------
// gdiag[h,d] = sum_i A[h,i,d]^2 + exp(log_lambda[h])
// ---------------------------------------------------------------------------
__global__ void gdiag_kernel(const float* __restrict__ A,
                             const float* __restrict__ log_lambda) {
    int i = blockIdx.x * blockDim.x + threadIdx.x;
    if (i >= Hc * HDc) return;
    int h = i >> 6, d = i & 63;
    float s = expf(log_lambda[h]);
#pragma unroll
    for (int r = 0; r < 16; r++) {
        float a = A[(h * 16 + r) * HDc + d];
        s = fmaf(a, a, s);
    }
    g_gdiag[i] = s;
}

// ---------------------------------------------------------------------------
// ksum[bh,d] = sum_t k[bh,d,t]   (k is (b,h,d,t) so rows are contiguous)
// one warp per row
// ---------------------------------------------------------------------------
__global__ void ksum_kernel() {
    int warp = (blockIdx.x * blockDim.x + threadIdx.x) >> 5;
    int lane = threadIdx.x & 31;
    if (warp >= Bc * Hc * HDc) return;
    const float* row = g_k + (size_t)warp * Tc;
    float s = 0.f;
    for (int t = lane; t < Tc; t += 32) s += row[t];
#pragma unroll
    for (int off = 16; off; off >>= 1)
        s += __shfl_xor_sync(0xffffffffu, s, off);
    if (lane == 0) g_ksum[warp] = s;
}

// ---------------------------------------------------------------------------
// SGEMM: Y[m,n] = sum_k X[m,k] * W[n,k] + bias[n]
// M=4096, N=K=1024. 128x128 block tile, BK=8, 256 threads, 8x8 micro-tile.
// outsel: 0 -> g_q (head t-major), 1 -> g_k (head d-major / transposed),
//         2 -> g_v (head t-major), 3 -> Yext flat (m*N+n)
// insel:  0 -> Xext, 1 -> g_o
// ---------------------------------------------------------------------------
__global__ __launch_bounds__(256) void gemm_kernel(
    const float* __restrict__ Xext, const float* __restrict__ W,
    const float* __restrict__ bias, float* __restrict__ Yext,
    int insel, int outsel)
{
    const int K = Dc, N = Dc;
    const float* X = insel ? g_o : Xext;

    __shared__ float As[8][128];
    __shared__ float Bs[8][128];

    int tid = threadIdx.x;
    int m0 = blockIdx.x * 128;
    int n0 = blockIdx.y * 128;
    int ty = tid >> 4, tx = tid & 15;
    int lrow = tid >> 1;
    int lcol = (tid & 1) * 4;

    float acc[8][8];
#pragma unroll
    for (int i = 0; i < 8; i++)
#pragma unroll
        for (int j = 0; j < 8; j++) acc[i][j] = 0.f;

    for (int k0 = 0; k0 < K; k0 += 8) {
        float4 a4 = *(const float4*)(X + (size_t)(m0 + lrow) * K + k0 + lcol);
        float4 b4 = *(const float4*)(W + (size_t)(n0 + lrow) * K + k0 + lcol);
        As[lcol + 0][lrow] = a4.x; As[lcol + 1][lrow] = a4.y;
        As[lcol + 2][lrow] = a4.z; As[lcol + 3][lrow] = a4.w;
        Bs[lcol + 0][lrow] = b4.x; Bs[lcol + 1][lrow] = b4.y;
        Bs[lcol + 2][lrow] = b4.z; Bs[lcol + 3][lrow] = b4.w;
        __syncthreads();
#pragma unroll
        for (int kk = 0; kk < 8; kk++) {
            float a[8], b[8];
            *(float4*)(a)     = *(const float4*)&As[kk][ty * 4];
            *(float4*)(a + 4) = *(const float4*)&As[kk][64 + ty * 4];
            *(float4*)(b)     = *(const float4*)&Bs[kk][tx * 4];
            *(float4*)(b + 4) = *(const float4*)&Bs[kk][64 + tx * 4];
#pragma unroll
            for (int i = 0; i < 8; i++)
#pragma unroll
                for (int j = 0; j < 8; j++)
                    acc[i][j] = fmaf(a[i], b[j], acc[i][j]);
        }
        __syncthreads();
    }

    float* Yq = g_q; float* Yk = g_k; float* Yv = g_v;
#pragma unroll
    for (int i = 0; i < 8; i++) {
        int mi = m0 + ((i < 4) ? (ty * 4 + i) : (64 + ty * 4 + i - 4));
        int bb = mi >> 11;      // batch
        int t  = mi & 2047;     // token
#pragma unroll
        for (int j = 0; j < 8; j++) {
            int nj = n0 + ((j < 4) ? (tx * 4 + j) : (64 + tx * 4 + j - 4));
            float val = acc[i][j] + bias[nj];
            if (outsel == 3) {
                Yext[(size_t)mi * N + nj] = val;
            } else {
                int h = nj >> 6, d = nj & 63;
                if (outsel == 1) {
                    Yk[((size_t)(bb * Hc + h) * HDc + d) * Tc + t] = val;
                } else {
                    float* Y = (outsel == 0) ? Yq : Yv;
                    Y[((size_t)(bb * Hc + h) * Tc + t) * HDc + d] = val;
                }
            }
        }
    }
}

// ---------------------------------------------------------------------------
// Flash attention per (b,h): logits = Sg . k, online softmax, o = attn @ v
// Sg[t,d] = (T*q[t,d] - ksum[d]) * gdiag[h,d]
// Block: 64-query tile vs all 2048 keys in 64-wide tiles.
// 256 threads as 16x16; each thread owns a 4(query)x4 micro-tile.
// smem: Sg[64][64] (q-major), K[64][64] (d-major, reused for P[q][j]),
//       V[64][64] (j-major). Total exactly 48KB static.
// ---------------------------------------------------------------------------
__global__ __launch_bounds__(256) void attn_kernel() {
    __shared__ float Sg_s[64 * 64];   // [q][d]
    __shared__ float K_s[64 * 64];    // [d][j]; later P[q][j]
    __shared__ float V_s[64 * 64];    // [j][d]

    int bh = blockIdx.y;
    int h  = bh & (Hc - 1);
    int q0 = blockIdx.x * 64;
    int tid = threadIdx.x;
    int ty = tid >> 4, tx = tid & 15;

    const float* qbase = g_q + ((size_t)bh * Tc + q0) * HDc;
    const float* ks    = g_ksum + bh * HDc;
    const float* gd    = g_gdiag + h * HDc;
    const float* kbase = g_k + (size_t)bh * HDc * Tc;
    const float* vbase = g_v + (size_t)bh * Tc * HDc;

    for (int idx = tid; idx < 64 * 64; idx += 256) {
        int t = idx >> 6, d = idx & 63;
        Sg_s[idx] = (2048.0f * qbase[t * HDc + d] - ks[d]) * gd[d];
    }

    float m_i[4], l_i[4], o_acc[4][4];
#pragma unroll
    for (int i = 0; i < 4; i++) {
        m_i[i] = -CUDART_INF_F;
        l_i[i] = 0.f;
#pragma unroll
        for (int j = 0; j < 4; j++) o_acc[i][j] = 0.f;
    }

    for (int kt = 0; kt < Tc; kt += 64) {
        __syncthreads();   // prior P/V consumers done (and Sg stores on iter 0)
        for (int idx = tid; idx < 64 * 64; idx += 256) {
            int d = idx >> 6, j = idx & 63;
            K_s[idx] = kbase[(size_t)d * Tc + kt + j];
            V_s[idx] = vbase[(size_t)(kt + d) * HDc + j];  // here d=row=j_key, j=col=dim
        }
        __syncthreads();

        // S = Sg @ K^T  (4x4 micro-tile per thread)
        float s[4][4];
#pragma unroll
        for (int i = 0; i < 4; i++)
#pragma unroll
            for (int j = 0; j < 4; j++) s[i][j] = 0.f;
#pragma unroll 8
        for (int d = 0; d < 64; d++) {
            float a[4], b[4];
#pragma unroll
            for (int i = 0; i < 4; i++) a[i] = Sg_s[(ty * 4 + i) * 64 + d];
#pragma unroll
            for (int j = 0; j < 4; j++) b[j] = K_s[d * 64 + tx * 4 + j];
#pragma unroll
            for (int i = 0; i < 4; i++)
#pragma unroll
                for (int j = 0; j < 4; j++)
                    s[i][j] = fmaf(a[i], b[j], s[i][j]);
        }

        // online softmax (row groups of 16 lanes share a query row)
        float p[4][4];
#pragma unroll
        for (int i = 0; i < 4; i++) {
            float rm = s[i][0];
#pragma unroll
            for (int j = 1; j < 4; j++) rm = fmaxf(rm, s[i][j]);
#pragma unroll
            for (int off = 1; off < 16; off <<= 1)
                rm = fmaxf(rm, __shfl_xor_sync(0xffffffffu, rm, off));
            float mn = fmaxf(m_i[i], rm);
            float scale = __expf(m_i[i] - mn);
            float rs = 0.f;
#pragma unroll
            for (int j = 0; j < 4; j++) {
                p[i][j] = __expf(s[i][j] - mn);
                rs += p[i][j];
            }
#pragma unroll
            for (int off = 1; off < 16; off <<= 1)
                rs += __shfl_xor_sync(0xffffffffu, rs, off);
            l_i[i] = l_i[i] * scale + rs;
            m_i[i] = mn;
#pragma unroll
            for (int j = 0; j < 4; j++) o_acc[i][j] *= scale;
        }

        __syncthreads();   // all K_s readers done
        // stage P into K_s as [q][j]
#pragma unroll
        for (int i = 0; i < 4; i++)
#pragma unroll
            for (int j = 0; j < 4; j++)
                K_s[(ty * 4 + i) * 64 + tx * 4 + j] = p[i][j];
        __syncthreads();

        // O += P @ V
#pragma unroll 8
        for (int j = 0; j < 64; j++) {
            float pv[4], vv[4];
#pragma unroll
            for (int i = 0; i < 4; i++) pv[i] = K_s[(ty * 4 + i) * 64 + j];
#pragma unroll
            for (int jd = 0; jd < 4; jd++) vv[jd] = V_s[j * 64 + tx * 4 + jd];
#pragma unroll
            for (int i = 0; i < 4; i++)
#pragma unroll
                for (int jd = 0; jd < 4; jd++)
                    o_acc[i][jd] = fmaf(pv[i], vv[jd], o_acc[i][jd]);
        }
    }

    // write O (merge heads into (b,t,d) layout)
    int b = bh >> 4;
#pragma unroll
    for (int i = 0; i < 4; i++) {
        float inv = 1.0f / l_i[i];
        size_t row = (size_t)(b * Tc + q0 + ty * 4 + i) * Dc + h * HDc + tx * 4;
#pragma unroll
        for (int jd = 0; jd < 4; jd++)
            g_o[row + jd] = o_acc[i][jd] * inv;
    }
}

// ---------------------------------------------------------------------------
extern "C" void kernel_launch(void* const* d_in, const int* in_sizes, int n_in,
                              void* d_out, int out_size) {
    const float* x   = (const float*)d_in[0];
    const float* Wq  = (const float*)d_in[1];
    const float* bq  = (const float*)d_in[2];
    const float* Wk  = (const float*)d_in[3];
    const float* bk  = (const float*)d_in[4];
    const float* Wv  = (const float*)d_in[5];
    const float* bv  = (const float*)d_in[6];
    const float* Wo  = (const float*)d_in[7];
    const float* bo  = (const float*)d_in[8];
    const float* A   = (const float*)d_in[9];
    const float* ll  = (const float*)d_in[10];
    float* out = (float*)d_out;

    dim3 ggrid(Mc / 128, Dc / 128);   // (32, 8)
    gemm_kernel<<<ggrid, 256>>>(x, Wq, bq, nullptr, 0, 0);  // q  (b,h,t,hd)
    gemm_kernel<<<ggrid, 256>>>(x, Wk, bk, nullptr, 0, 1);  // k  (b,h,hd,t)
    gemm_kernel<<<ggrid, 256>>>(x, Wv, bv, nullptr, 0, 2);  // v  (b,h,t,hd)
    gdiag_kernel<<<4, 256>>>(A, ll);
    ksum_kernel<<<(Bc * Hc * HDc * 32) / 256, 256>>>();
    attn_kernel<<<dim3(Tc / 64, Bc * Hc), 256>>>();
    gemm_kernel<<<ggrid, 256>>>(nullptr, Wo, bo, out, 1, 3); // out projection
}

// round 3
// speedup vs baseline: 1.3132x; 1.3132x over previous
#include <cuda_runtime.h>
#include <cuda_bf16.h>
#include <math_constants.h>
#include <cstdint>

#define Bc 2
#define Tc 2048
#define Dc 1024
#define Hc 16
#define HDc 64
#define Mc (Bc*Tc)

#define KTOT 3072          // tripled K for split-bf16 3-product GEMM
#define BM 128
#define BN 128
#define BK 32              // bf16 elements per K chunk
#define NK (KTOT/BK)       // 96
#define LDS_ROW 40         // padded row stride in bf16 elements (80 bytes)
#define STG_HALF (128*LDS_ROW*2)          // bytes per operand per stage (10240)
#define STG_BYTES (2*STG_HALF)            // 20480
#define STAGES 3
#define SMEM_DYN (STAGES*STG_BYTES)       // 61440

// ---------------- scratch (device globals; no runtime allocation) ----------
__device__ __align__(16) float g_q[Bc*Hc*Tc*HDc];     // (b,h,t,hd)
__device__ __align__(16) float g_k[Bc*Hc*HDc*Tc];     // (b,h,hd,t) transposed
__device__ __align__(16) float g_v[Bc*Hc*Tc*HDc];     // (b,h,t,hd)
__device__ __align__(16) float g_o[Bc*Tc*Dc];         // (b,t,d)
__device__ __align__(16) float g_ksum[Bc*Hc*HDc];
__device__ __align__(16) float g_gdiag[Hc*HDc];
__device__ __align__(16) __nv_bfloat16 g_x2[Mc*KTOT];       // [hi|hi|lo] of x
__device__ __align__(16) __nv_bfloat16 g_w2[4][Dc*KTOT];    // [hi|lo|hi] of W
__device__ __align__(16) __nv_bfloat16 g_o2[Mc*KTOT];       // [hi|hi|lo] of o

// ---------------- PTX helpers ----------------------------------------------
__device__ __forceinline__ uint32_t smem_u32(const void* p) {
    uint32_t a;
    asm("{ .reg .u64 t; cvta.to.shared.u64 t, %1; cvt.u32.u64 %0, t; }" : "=r"(a) : "l"(p));
    return a;
}
#define CP_ASYNC16(sm, gm) \
    asm volatile("cp.async.cg.shared.global [%0], [%1], 16;" :: "r"(sm), "l"(gm))
#define CP_COMMIT() asm volatile("cp.async.commit_group;" ::: "memory")
#define CP_WAIT(n)  asm volatile("cp.async.wait_group %0;" :: "n"(n) : "memory")

__device__ __forceinline__ void ldsm_x4(uint32_t& r0, uint32_t& r1,
                                        uint32_t& r2, uint32_t& r3, uint32_t addr) {
    asm volatile("ldmatrix.sync.aligned.m8n8.x4.shared.b16 {%0,%1,%2,%3}, [%4];"
                 : "=r"(r0), "=r"(r1), "=r"(r2), "=r"(r3) : "r"(addr));
}
__device__ __forceinline__ void mma16816(float* c, const uint32_t* a, const uint32_t* b) {
    asm volatile(
        "mma.sync.aligned.m16n8k16.row.col.f32.bf16.bf16.f32 "
        "{%0,%1,%2,%3}, {%4,%5,%6,%7}, {%8,%9}, {%0,%1,%2,%3};"
        : "+f"(c[0]), "+f"(c[1]), "+f"(c[2]), "+f"(c[3])
        : "r"(a[0]), "r"(a[1]), "r"(a[2]), "r"(a[3]), "r"(b[0]), "r"(b[1]));
}

// ---------------------------------------------------------------------------
// split fp32 -> bf16 triple. mode 0 ("A"): [hi | hi | lo]; mode 1 ("B"):
// [hi | lo | hi].  A'·B' over tripled K = hi·hi + hi·lo + lo·hi ~ fp32 product.
// ---------------------------------------------------------------------------
__global__ void split_kernel(const float* __restrict__ src,
                             __nv_bfloat16* __restrict__ dst, int rows, int mode) {
    int idx = blockIdx.x * blockDim.x + threadIdx.x;
    if (idx >= rows * (Dc/2)) return;
    float2 v = ((const float2*)src)[idx];
    int r = idx / (Dc/2), c2 = idx % (Dc/2);
    __nv_bfloat162 hi, lo;
    hi.x = __float2bfloat16(v.x); hi.y = __float2bfloat16(v.y);
    lo.x = __float2bfloat16(v.x - __bfloat162float(hi.x));
    lo.y = __float2bfloat16(v.y - __bfloat162float(hi.y));
    __nv_bfloat162* d = (__nv_bfloat162*)(dst + (size_t)r * KTOT);
    if (mode == 0) { d[c2] = hi; d[512 + c2] = hi; d[1024 + c2] = lo; }
    else           { d[c2] = hi; d[512 + c2] = lo; d[1024 + c2] = hi; }
}

// ---------------------------------------------------------------------------
// mma.sync bf16 GEMM: C[4096,1024] = A2[4096,3072] @ W2[1024,3072]^T + bias
// 128x128 tile, BK=32, 3-stage cp.async, 8 warps (warp tile 32x64).
// outsel: 0 -> g_q, 1 -> g_k (transposed), 2 -> g_v, 3 -> Yext flat
// ---------------------------------------------------------------------------
__global__ __launch_bounds__(256)
void gemm_tc(const __nv_bfloat16* __restrict__ A2, const __nv_bfloat16* __restrict__ W2,
             const float* __restrict__ bias, float* __restrict__ Yext, int outsel)
{
    extern __shared__ __align__(16) char dsmem[];
    uint32_t base = smem_u32(dsmem);

    int tid = threadIdx.x, wid = tid >> 5, lane = tid & 31;
    int wm = wid & 3, wn = wid >> 2;               // 4x2 warp grid
    int m0 = blockIdx.x * BM, n0 = blockIdx.y * BN;

    const __nv_bfloat16* gA = A2 + (size_t)m0 * KTOT;
    const __nv_bfloat16* gW = W2 + (size_t)n0 * KTOT;

    // chunk loader: 128 rows x 32 cols of A and W into stage s
    auto load_chunk = [&](int c) {
        uint32_t sa = base + (c % STAGES) * STG_BYTES;
        uint32_t sb = sa + STG_HALF;
        int k0 = c * BK;
#pragma unroll
        for (int it = 0; it < 2; it++) {
            int ch = tid + it * 256;               // 512 chunks of 16B
            int r = ch >> 2, off = (ch & 3) * 8;   // row, element offset
            CP_ASYNC16(sa + r * (LDS_ROW*2) + off * 2,
                       (const char*)(gA + (size_t)r * KTOT + k0 + off));
            CP_ASYNC16(sb + r * (LDS_ROW*2) + off * 2,
                       (const char*)(gW + (size_t)r * KTOT + k0 + off));
        }
        CP_COMMIT();
    };

    float acc[2][8][4];
#pragma unroll
    for (int i = 0; i < 2; i++)
#pragma unroll
        for (int j = 0; j < 8; j++)
#pragma unroll
            for (int l = 0; l < 4; l++) acc[i][j][l] = 0.f;

    load_chunk(0);
    load_chunk(1);

    // ldmatrix source addresses (element offsets precomputed per lane)
    int a_row = wm * 32 + (lane & 15);
    int a_col8 = (lane >> 4) * 8;
    int b_row = wn * 64 + (lane & 7) + ((lane >> 4) << 3);
    int b_col8 = ((lane >> 3) & 1) * 8;

#pragma unroll 1
    for (int i = 0; i < NK; i++) {
        CP_WAIT(1);
        __syncthreads();
        if (i + 2 < NK) load_chunk(i + 2);

        uint32_t sa = base + (i % STAGES) * STG_BYTES;
        uint32_t sb = sa + STG_HALF;
#pragma unroll
        for (int kk = 0; kk < 2; kk++) {
            uint32_t a[2][4], b[8][2];
#pragma unroll
            for (int mf = 0; mf < 2; mf++)
                ldsm_x4(a[mf][0], a[mf][1], a[mf][2], a[mf][3],
                        sa + ((a_row + mf*16) * LDS_ROW + kk*16 + a_col8) * 2);
#pragma unroll
            for (int np = 0; np < 4; np++)
                ldsm_x4(b[2*np][0], b[2*np][1], b[2*np+1][0], b[2*np+1][1],
                        sb + ((b_row + np*16) * LDS_ROW + kk*16 + b_col8) * 2);
#pragma unroll
            for (int mf = 0; mf < 2; mf++)
#pragma unroll
                for (int nf = 0; nf < 8; nf++)
                    mma16816(acc[mf][nf], a[mf], b[nf]);
        }
        __syncthreads();
    }

    // epilogue: c0,c1 -> (m, n..n+1); c2,c3 -> (m+8, n..n+1)
#pragma unroll
    for (int mf = 0; mf < 2; mf++) {
#pragma unroll
        for (int nf = 0; nf < 8; nf++) {
            int m = m0 + wm*32 + mf*16 + (lane >> 2);
            int n = n0 + wn*64 + nf*8 + 2*(lane & 3);
            float b0 = bias[n], b1 = bias[n+1];
#pragma unroll
            for (int half = 0; half < 2; half++) {
                int mm = m + half * 8;
                float v0 = acc[mf][nf][half*2+0] + b0;
                float v1 = acc[mf][nf][half*2+1] + b1;
                int bb = mm >> 11, t = mm & 2047;
                int h = n >> 6, d = n & 63;
                if (outsel == 3) {
                    *(float2*)(Yext + (size_t)mm * Dc + n) = make_float2(v0, v1);
                } else if (outsel == 1) {
                    float* dst = g_k + ((size_t)(bb*Hc + h) * HDc + d) * Tc + t;
                    dst[0] = v0; dst[Tc] = v1;
                } else {
                    float* Y = (outsel == 0) ? g_q : g_v;
                    *(float2*)(Y + ((size_t)(bb*Hc + h) * Tc + t) * HDc + d) =
                        make_float2(v0, v1);
                }
            }
        }
    }
}

// ---------------------------------------------------------------------------
__global__ void gdiag_kernel(const float* __restrict__ A,
                             const float* __restrict__ log_lambda) {
    int i = blockIdx.x * blockDim.x + threadIdx.x;
    if (i >= Hc * HDc) return;
    int h = i >> 6, d = i & 63;
    float s = expf(log_lambda[h]);
#pragma unroll
    for (int r = 0; r < 16; r++) {
        float a = A[(h * 16 + r) * HDc + d];
        s = fmaf(a, a, s);
    }
    g_gdiag[i] = s;
}

__global__ void ksum_kernel() {
    int warp = (blockIdx.x * blockDim.x + threadIdx.x) >> 5;
    int lane = threadIdx.x & 31;
    if (warp >= Bc * Hc * HDc) return;
    const float* row = g_k + (size_t)warp * Tc;
    float s = 0.f;
    for (int t = lane; t < Tc; t += 32) s += row[t];
#pragma unroll
    for (int off = 16; off; off >>= 1)
        s += __shfl_xor_sync(0xffffffffu, s, off);
    if (lane == 0) g_ksum[warp] = s;
}

// ---------------------------------------------------------------------------
// Flash attention per (b,h): logits = Sg . k, online softmax, o = attn @ v
// (fp32 path; mma conversion is the next candidate once HMMA rate is measured)
// ---------------------------------------------------------------------------
__global__ __launch_bounds__(256) void attn_kernel() {
    __shared__ float Sg_s[64 * 64];
    __shared__ float K_s[64 * 64];
    __shared__ float V_s[64 * 64];

    int bh = blockIdx.y;
    int h  = bh & (Hc - 1);
    int q0 = blockIdx.x * 64;
    int tid = threadIdx.x;
    int ty = tid >> 4, tx = tid & 15;

    const float* qbase = g_q + ((size_t)bh * Tc + q0) * HDc;
    const float* ks    = g_ksum + bh * HDc;
    const float* gd    = g_gdiag + h * HDc;
    const float* kbase = g_k + (size_t)bh * HDc * Tc;
    const float* vbase = g_v + (size_t)bh * Tc * HDc;

    for (int idx = tid; idx < 64 * 64; idx += 256) {
        int t = idx >> 6, d = idx & 63;
        Sg_s[idx] = (2048.0f * qbase[t * HDc + d] - ks[d]) * gd[d];
    }

    float m_i[4], l_i[4], o_acc[4][4];
#pragma unroll
    for (int i = 0; i < 4; i++) {
        m_i[i] = -CUDART_INF_F;
        l_i[i] = 0.f;
#pragma unroll
        for (int j = 0; j < 4; j++) o_acc[i][j] = 0.f;
    }

    for (int kt = 0; kt < Tc; kt += 64) {
        __syncthreads();
        for (int idx = tid; idx < 64 * 64; idx += 256) {
            int d = idx >> 6, j = idx & 63;
            K_s[idx] = kbase[(size_t)d * Tc + kt + j];
            V_s[idx] = vbase[(size_t)(kt + d) * HDc + j];
        }
        __syncthreads();

        float s[4][4];
#pragma unroll
        for (int i = 0; i < 4; i++)
#pragma unroll
            for (int j = 0; j < 4; j++) s[i][j] = 0.f;
#pragma unroll 8
        for (int d = 0; d < 64; d++) {
            float a[4], b[4];
#pragma unroll
            for (int i = 0; i < 4; i++) a[i] = Sg_s[(ty * 4 + i) * 64 + d];
#pragma unroll
            for (int j = 0; j < 4; j++) b[j] = K_s[d * 64 + tx * 4 + j];
#pragma unroll
            for (int i = 0; i < 4; i++)
#pragma unroll
                for (int j = 0; j < 4; j++)
                    s[i][j] = fmaf(a[i], b[j], s[i][j]);
        }

        float p[4][4];
#pragma unroll
        for (int i = 0; i < 4; i++) {
            float rm = s[i][0];
#pragma unroll
            for (int j = 1; j < 4; j++) rm = fmaxf(rm, s[i][j]);
#pragma unroll
            for (int off = 1; off < 16; off <<= 1)
                rm = fmaxf(rm, __shfl_xor_sync(0xffffffffu, rm, off));
            float mn = fmaxf(m_i[i], rm);
            float scale = __expf(m_i[i] - mn);
            float rs = 0.f;
#pragma unroll
            for (int j = 0; j < 4; j++) {
                p[i][j] = __expf(s[i][j] - mn);
                rs += p[i][j];
            }
#pragma unroll
            for (int off = 1; off < 16; off <<= 1)
                rs += __shfl_xor_sync(0xffffffffu, rs, off);
            l_i[i] = l_i[i] * scale + rs;
            m_i[i] = mn;
#pragma unroll
            for (int j = 0; j < 4; j++) o_acc[i][j] *= scale;
        }

        __syncthreads();
#pragma unroll
        for (int i = 0; i < 4; i++)
#pragma unroll
            for (int j = 0; j < 4; j++)
                K_s[(ty * 4 + i) * 64 + tx * 4 + j] = p[i][j];
        __syncthreads();

#pragma unroll 8
        for (int j = 0; j < 64; j++) {
            float pv[4], vv[4];
#pragma unroll
            for (int i = 0; i < 4; i++) pv[i] = K_s[(ty * 4 + i) * 64 + j];
#pragma unroll
            for (int jd = 0; jd < 4; jd++) vv[jd] = V_s[j * 64 + tx * 4 + jd];
#pragma unroll
            for (int i = 0; i < 4; i++)
#pragma unroll
                for (int jd = 0; jd < 4; jd++)
                    o_acc[i][jd] = fmaf(pv[i], vv[jd], o_acc[i][jd]);
        }
    }

    int b = bh >> 4;
#pragma unroll
    for (int i = 0; i < 4; i++) {
        float inv = 1.0f / l_i[i];
        size_t row = (size_t)(b * Tc + q0 + ty * 4 + i) * Dc + h * HDc + tx * 4;
#pragma unroll
        for (int jd = 0; jd < 4; jd++)
            g_o[row + jd] = o_acc[i][jd] * inv;
    }
}

// ---------------------------------------------------------------------------
extern "C" void kernel_launch(void* const* d_in, const int* in_sizes, int n_in,
                              void* d_out, int out_size) {
    const float* x   = (const float*)d_in[0];
    const float* Wq  = (const float*)d_in[1];
    const float* bq  = (const float*)d_in[2];
    const float* Wk  = (const float*)d_in[3];
    const float* bk  = (const float*)d_in[4];
    const float* Wv  = (const float*)d_in[5];
    const float* bv  = (const float*)d_in[6];
    const float* Wo  = (const float*)d_in[7];
    const float* bo  = (const float*)d_in[8];
    const float* A   = (const float*)d_in[9];
    const float* ll  = (const float*)d_in[10];
    float* out = (float*)d_out;

    cudaFuncSetAttribute(gemm_tc, cudaFuncAttributeMaxDynamicSharedMemorySize, SMEM_DYN);

    __nv_bfloat16 *x2, *w2q, *w2k, *w2v, *w2o, *o2;
    float* o_ptr;
    cudaGetSymbolAddress((void**)&x2,  g_x2);
    cudaGetSymbolAddress((void**)&w2q, g_w2);
    cudaGetSymbolAddress((void**)&o2,  g_o2);
    cudaGetSymbolAddress((void**)&o_ptr, g_o);
    w2k = w2q + (size_t)Dc*KTOT; w2v = w2k + (size_t)Dc*KTOT; w2o = w2v + (size_t)Dc*KTOT;

    const float* Ws[4] = {Wq, Wk, Wv, Wo};
    __nv_bfloat16* W2s[4] = {w2q, w2k, w2v, w2o};

    split_kernel<<<(Mc*Dc/2 + 255)/256, 256>>>(x, x2, Mc, 0);
    for (int i = 0; i < 4; i++)
        split_kernel<<<(Dc*Dc/2 + 255)/256, 256>>>(Ws[i], W2s[i], Dc, 1);

    dim3 ggrid(Mc / BM, Dc / BN);   // (32, 8)
    gemm_tc<<<ggrid, 256, SMEM_DYN>>>(x2, w2q, bq, nullptr, 0);  // q
    gemm_tc<<<ggrid, 256, SMEM_DYN>>>(x2, w2k, bk, nullptr, 1);  // k (transposed)
    gemm_tc<<<ggrid, 256, SMEM_DYN>>>(x2, w2v, bv, nullptr, 2);  // v

    gdiag_kernel<<<4, 256>>>(A, ll);
    ksum_kernel<<<(Bc * Hc * HDc * 32) / 256, 256>>>();
    attn_kernel<<<dim3(Tc / 64, Bc * Hc), 256>>>();

    split_kernel<<<(Mc*Dc/2 + 255)/256, 256>>>(o_ptr, o2, Mc, 0);
    gemm_tc<<<ggrid, 256, SMEM_DYN>>>(o2, w2o, bo, out, 3);      // out projection
}

// round 4
// speedup vs baseline: 2.2052x; 1.6793x over previous
#include <cuda_runtime.h>
#include <cuda_bf16.h>
#include <math_constants.h>
#include <cstdint>

#define Bc 2
#define Tc 2048
#define Dc 1024
#define Hc 16
#define HDc 64
#define Mc (Bc*Tc)

#define KTOT 3072          // tripled K for split-bf16 3-product GEMM
#define BM 128
#define BN 128
#define BK 32
#define NK (KTOT/BK)       // 96
#define LDS_ROW 40
#define STG_HALF (128*LDS_ROW*2)
#define STG_BYTES (2*STG_HALF)
#define STAGES 3
#define SMEM_DYN (STAGES*STG_BYTES)       // 61440

// attention tiling
#define AT_M 128
#define LDSA 200                           // padded row (elems) for Sg2/K2 tiles
#define LDV  72                            // padded row (elems) for V^T tiles
#define SG_BYTES_A (128*LDSA*2)            // 51200
#define K2STG (64*LDSA*2)                  // 25600
#define VTSTG (128*LDV*2)                  // 18432
#define ASMEM (SG_BYTES_A + 2*K2STG + 2*VTSTG)  // 139264

// ---------------- scratch (device globals; no runtime allocation) ----------
__device__ __align__(16) float g_q[Bc*Hc*Tc*HDc];      // (b,h,t,hd) fp32
__device__ __align__(16) float g_o[Bc*Tc*Dc];          // (b,t,d) fp32
__device__ __align__(16) float g_ksum[Bc*Hc*HDc];
__device__ __align__(16) float g_gdiag[Hc*HDc];
__device__ __align__(16) __nv_bfloat16 g_x2[Mc*KTOT];        // [hi|hi|lo] of x
__device__ __align__(16) __nv_bfloat16 g_w2[4][Dc*KTOT];     // [hi|lo|hi] of W
__device__ __align__(16) __nv_bfloat16 g_o2[Mc*KTOT];        // [hi|hi|lo] of o
__device__ __align__(16) __nv_bfloat16 g_k2[Bc*Hc*Tc*192];   // [hi|lo|hi] key rows
__device__ __align__(16) __nv_bfloat16 g_sg2[Bc*Hc*Tc*192];  // [hi|hi|lo] Sg rows
__device__ __align__(16) __nv_bfloat16 g_v2t[Bc*Hc*2*HDc*Tc];// [bh][hi/lo][d][t]

// ---------------- PTX helpers ----------------------------------------------
__device__ __forceinline__ uint32_t smem_u32(const void* p) {
    uint32_t a;
    asm("{ .reg .u64 t; cvta.to.shared.u64 t, %1; cvt.u32.u64 %0, t; }" : "=r"(a) : "l"(p));
    return a;
}
#define CP_ASYNC16(sm, gm) \
    asm volatile("cp.async.cg.shared.global [%0], [%1], 16;" :: "r"(sm), "l"(gm))
#define CP_COMMIT() asm volatile("cp.async.commit_group;" ::: "memory")
#define CP_WAIT(n)  asm volatile("cp.async.wait_group %0;" :: "n"(n) : "memory")

__device__ __forceinline__ void ldsm_x4(uint32_t& r0, uint32_t& r1,
                                        uint32_t& r2, uint32_t& r3, uint32_t addr) {
    asm volatile("ldmatrix.sync.aligned.m8n8.x4.shared.b16 {%0,%1,%2,%3}, [%4];"
                 : "=r"(r0), "=r"(r1), "=r"(r2), "=r"(r3) : "r"(addr));
}
__device__ __forceinline__ void mma16816(float* c, const uint32_t* a, const uint32_t* b) {
    asm volatile(
        "mma.sync.aligned.m16n8k16.row.col.f32.bf16.bf16.f32 "
        "{%0,%1,%2,%3}, {%4,%5,%6,%7}, {%8,%9}, {%0,%1,%2,%3};"
        : "+f"(c[0]), "+f"(c[1]), "+f"(c[2]), "+f"(c[3])
        : "r"(a[0]), "r"(a[1]), "r"(a[2]), "r"(a[3]), "r"(b[0]), "r"(b[1]));
}
// pack two fp32 -> bf16x2 (lo = first arg)
__device__ __forceinline__ uint32_t pkbf(float lo, float hi) {
    uint32_t r;
    asm("cvt.rn.bf16x2.f32 %0, %1, %2;" : "=r"(r) : "f"(hi), "f"(lo));
    return r;
}
__device__ __forceinline__ float bfr(float x) {           // round-to-bf16 value
    return __bfloat162float(__float2bfloat16(x));
}

// ---------------------------------------------------------------------------
// split fp32 -> bf16 triple. mode 0 (A): [hi|hi|lo]; mode 1 (B): [hi|lo|hi].
// ---------------------------------------------------------------------------
__global__ void split_kernel(const float* __restrict__ src,
                             __nv_bfloat16* __restrict__ dst, int rows, int mode) {
    int idx = blockIdx.x * blockDim.x + threadIdx.x;
    if (idx >= rows * (Dc/2)) return;
    float2 v = ((const float2*)src)[idx];
    int r = idx / (Dc/2), c2 = idx % (Dc/2);
    __nv_bfloat162 hi, lo;
    hi.x = __float2bfloat16(v.x); hi.y = __float2bfloat16(v.y);
    lo.x = __float2bfloat16(v.x - __bfloat162float(hi.x));
    lo.y = __float2bfloat16(v.y - __bfloat162float(hi.y));
    __nv_bfloat162* d = (__nv_bfloat162*)(dst + (size_t)r * KTOT);
    if (mode == 0) { d[c2] = hi; d[512 + c2] = hi; d[1024 + c2] = lo; }
    else           { d[c2] = hi; d[512 + c2] = lo; d[1024 + c2] = hi; }
}

// ---------------------------------------------------------------------------
// mma.sync bf16 GEMM: C[4096,1024] = A2 @ W2^T + bias
// outsel: 0 -> g_q fp32, 1 -> g_k2 triple, 2 -> g_v2t hi/lo planes, 3 -> Yext
// ---------------------------------------------------------------------------
__global__ __launch_bounds__(256)
void gemm_tc(const __nv_bfloat16* __restrict__ A2, const __nv_bfloat16* __restrict__ W2,
             const float* __restrict__ bias, float* __restrict__ Yext, int outsel)
{
    extern __shared__ __align__(16) char dsmem[];
    uint32_t base = smem_u32(dsmem);

    int tid = threadIdx.x, wid = tid >> 5, lane = tid & 31;
    int wm = wid & 3, wn = wid >> 2;
    int m0 = blockIdx.x * BM, n0 = blockIdx.y * BN;

    const __nv_bfloat16* gA = A2 + (size_t)m0 * KTOT;
    const __nv_bfloat16* gW = W2 + (size_t)n0 * KTOT;

    auto load_chunk = [&](int c) {
        uint32_t sa = base + (c % STAGES) * STG_BYTES;
        uint32_t sb = sa + STG_HALF;
        int k0 = c * BK;
#pragma unroll
        for (int it = 0; it < 2; it++) {
            int ch = tid + it * 256;
            int r = ch >> 2, off = (ch & 3) * 8;
            CP_ASYNC16(sa + r * (LDS_ROW*2) + off * 2,
                       (const char*)(gA + (size_t)r * KTOT + k0 + off));
            CP_ASYNC16(sb + r * (LDS_ROW*2) + off * 2,
                       (const char*)(gW + (size_t)r * KTOT + k0 + off));
        }
        CP_COMMIT();
    };

    float acc[2][8][4];
#pragma unroll
    for (int i = 0; i < 2; i++)
#pragma unroll
        for (int j = 0; j < 8; j++)
#pragma unroll
            for (int l = 0; l < 4; l++) acc[i][j][l] = 0.f;

    load_chunk(0);
    load_chunk(1);

    int a_row = wm * 32 + (lane & 15);
    int a_col8 = (lane >> 4) * 8;
    int b_row = wn * 64 + (lane & 7) + ((lane >> 4) << 3);
    int b_col8 = ((lane >> 3) & 1) * 8;

#pragma unroll 1
    for (int i = 0; i < NK; i++) {
        CP_WAIT(1);
        __syncthreads();
        if (i + 2 < NK) load_chunk(i + 2);

        uint32_t sa = base + (i % STAGES) * STG_BYTES;
        uint32_t sb = sa + STG_HALF;
#pragma unroll
        for (int kk = 0; kk < 2; kk++) {
            uint32_t a[2][4], b[8][2];
#pragma unroll
            for (int mf = 0; mf < 2; mf++)
                ldsm_x4(a[mf][0], a[mf][1], a[mf][2], a[mf][3],
                        sa + ((a_row + mf*16) * LDS_ROW + kk*16 + a_col8) * 2);
#pragma unroll
            for (int np = 0; np < 4; np++)
                ldsm_x4(b[2*np][0], b[2*np][1], b[2*np+1][0], b[2*np+1][1],
                        sb + ((b_row + np*16) * LDS_ROW + kk*16 + b_col8) * 2);
#pragma unroll
            for (int mf = 0; mf < 2; mf++)
#pragma unroll
                for (int nf = 0; nf < 8; nf++)
                    mma16816(acc[mf][nf], a[mf], b[nf]);
        }
        __syncthreads();
    }

#pragma unroll
    for (int mf = 0; mf < 2; mf++) {
#pragma unroll
        for (int nf = 0; nf < 8; nf++) {
            int m = m0 + wm*32 + mf*16 + (lane >> 2);
            int n = n0 + wn*64 + nf*8 + 2*(lane & 3);
            float b0 = bias[n], b1 = bias[n+1];
#pragma unroll
            for (int half = 0; half < 2; half++) {
                int mm = m + half * 8;
                float v0 = acc[mf][nf][half*2+0] + b0;
                float v1 = acc[mf][nf][half*2+1] + b1;
                int bb = mm >> 11, t = mm & 2047;
                int h = n >> 6, d = n & 63;
                int bh = bb * Hc + h;
                if (outsel == 3) {
                    *(float2*)(Yext + (size_t)mm * Dc + n) = make_float2(v0, v1);
                } else if (outsel == 0) {
                    *(float2*)(g_q + ((size_t)bh * Tc + t) * HDc + d) =
                        make_float2(v0, v1);
                } else if (outsel == 1) {
                    // key triple [hi|lo|hi]
                    __nv_bfloat16 h0 = __float2bfloat16(v0);
                    __nv_bfloat16 l0 = __float2bfloat16(v0 - __bfloat162float(h0));
                    __nv_bfloat16 h1 = __float2bfloat16(v1);
                    __nv_bfloat16 l1 = __float2bfloat16(v1 - __bfloat162float(h1));
                    __nv_bfloat16* row = g_k2 + ((size_t)bh * Tc + t) * 192;
                    row[d] = h0;   row[d+1] = h1;
                    row[64+d] = l0; row[64+d+1] = l1;
                    row[128+d] = h0; row[128+d+1] = h1;
                } else {
                    // V transposed hi/lo planes
                    __nv_bfloat16 h0 = __float2bfloat16(v0);
                    __nv_bfloat16 l0 = __float2bfloat16(v0 - __bfloat162float(h0));
                    __nv_bfloat16 h1 = __float2bfloat16(v1);
                    __nv_bfloat16 l1 = __float2bfloat16(v1 - __bfloat162float(h1));
                    __nv_bfloat16* pbase = g_v2t + (size_t)bh * 2 * HDc * Tc;
                    pbase[(size_t)d * Tc + t] = h0;
                    pbase[(size_t)(d+1) * Tc + t] = h1;
                    pbase[(size_t)(HDc + d) * Tc + t] = l0;
                    pbase[(size_t)(HDc + d+1) * Tc + t] = l1;
                }
            }
        }
    }
}

// ---------------------------------------------------------------------------
__global__ void gdiag_kernel(const float* __restrict__ A,
                             const float* __restrict__ log_lambda) {
    int i = blockIdx.x * blockDim.x + threadIdx.x;
    if (i >= Hc * HDc) return;
    int h = i >> 6, d = i & 63;
    float s = expf(log_lambda[h]);
#pragma unroll
    for (int r = 0; r < 16; r++) {
        float a = A[(h * 16 + r) * HDc + d];
        s = fmaf(a, a, s);
    }
    g_gdiag[i] = s;
}

// ksum[bh,d] = sum_t (k_hi + k_lo) from g_k2; one block per bh
__global__ __launch_bounds__(256) void ksum2_kernel() {
    __shared__ float red[256];
    int bh = blockIdx.x;
    int d = threadIdx.x & 63, chunk = threadIdx.x >> 6;
    const __nv_bfloat16* base = g_k2 + (size_t)bh * Tc * 192;
    float s = 0.f;
    for (int t = chunk * 512; t < (chunk + 1) * 512; t++) {
        const __nv_bfloat16* row = base + (size_t)t * 192;
        s += __bfloat162float(row[d]) + __bfloat162float(row[64 + d]);
    }
    red[threadIdx.x] = s;
    __syncthreads();
    if (chunk == 0) {
        float tot = red[d] + red[64+d] + red[128+d] + red[192+d];
        g_ksum[bh * HDc + d] = tot;
    }
}

// Sg[t,d] = (T*q - ksum)*gdiag, split to [hi|hi|lo] rows of 192
__global__ void sgprep_kernel() {
    int idx = blockIdx.x * blockDim.x + threadIdx.x;
    if (idx >= Bc*Hc*Tc*HDc) return;
    int bh = idx >> 17;
    int rem = idx & 131071;
    int t = rem >> 6, d = rem & 63;
    float q = g_q[((size_t)bh * Tc + t) * HDc + d];
    float sg = (2048.0f * q - g_ksum[bh * HDc + d]) * g_gdiag[(bh & 15) * HDc + d];
    __nv_bfloat16 hi = __float2bfloat16(sg);
    __nv_bfloat16 lo = __float2bfloat16(sg - __bfloat162float(hi));
    __nv_bfloat16* row = g_sg2 + ((size_t)bh * Tc + t) * 192;
    row[d] = hi; row[64 + d] = hi; row[128 + d] = lo;
}

// ---------------------------------------------------------------------------
// Tensor-core flash attention. CTA: 128 queries x (b,h); 8 warps, warp = 16 rows.
// QK over K=192 (split triple); softmax in C-frag layout; P split in regs;
// PV = Phi*Vhi + Phi*Vlo + Plo*Vhi over key tiles of 64.
// ---------------------------------------------------------------------------
__global__ __launch_bounds__(256, 1)
void attn_tc() {
    extern __shared__ __align__(16) char asmem[];
    uint32_t sgs = smem_u32(asmem);
    uint32_t k2s = sgs + SG_BYTES_A;
    uint32_t vts = k2s + 2 * K2STG;

    int tid = threadIdx.x, wid = tid >> 5, lane = tid & 31;
    int bh = blockIdx.y, h = bh & 15, b = bh >> 4;
    int q0 = blockIdx.x * AT_M;

    const __nv_bfloat16* sg_g = g_sg2 + ((size_t)bh * Tc + q0) * 192;
    const __nv_bfloat16* k_g  = g_k2  + (size_t)bh * Tc * 192;
    const __nv_bfloat16* v_g  = g_v2t + (size_t)bh * 2 * HDc * Tc;

    // preload Sg2 tile (128 rows x 192)
#pragma unroll
    for (int it = 0; it < 12; it++) {
        int id = tid + it * 256;
        int r = id / 24, c = id % 24;
        CP_ASYNC16(sgs + r * (LDSA*2) + c * 16, (const char*)(sg_g + (size_t)r * 192 + c * 8));
    }
    CP_COMMIT();

    auto load_tile = [&](int ti) {
        int st = ti & 1;
        int j0 = ti * 64;
        uint32_t kd = k2s + st * K2STG;
        uint32_t vd = vts + st * VTSTG;
#pragma unroll
        for (int it = 0; it < 6; it++) {          // K: 64 x 192
            int id = tid + it * 256;
            int r = id / 24, c = id % 24;
            CP_ASYNC16(kd + r * (LDSA*2) + c * 16,
                       (const char*)(k_g + (size_t)(j0 + r) * 192 + c * 8));
        }
#pragma unroll
        for (int it = 0; it < 4; it++) {          // V^T: 128 x 64
            int id = tid + it * 256;
            int r = id >> 3, c = id & 7;
            CP_ASYNC16(vd + r * (LDV*2) + c * 16,
                       (const char*)(v_g + (size_t)r * Tc + j0 + c * 8));
        }
        CP_COMMIT();
    };

    load_tile(0);
    CP_WAIT(1);
    __syncthreads();

    // hoist Sg2 A-fragments for all 12 k-chunks
    uint32_t aq[12][4];
    {
        int arow = wid * 16 + (lane & 15);
        int acol = (lane >> 4) * 8;
#pragma unroll
        for (int kc = 0; kc < 12; kc++)
            ldsm_x4(aq[kc][0], aq[kc][1], aq[kc][2], aq[kc][3],
                    sgs + (arow * LDSA + kc * 16 + acol) * 2);
    }

    float o_acc[8][4];
#pragma unroll
    for (int nf = 0; nf < 8; nf++)
#pragma unroll
        for (int l = 0; l < 4; l++) o_acc[nf][l] = 0.f;
    float m0 = -CUDART_INF_F, m1 = -CUDART_INF_F, l0 = 0.f, l1 = 0.f;

    int brow = (lane & 7) + ((lane >> 4) << 3);
    int bcol8 = ((lane >> 3) & 1) * 8;

#pragma unroll 1
    for (int ti = 0; ti < 32; ti++) {
        if (ti + 1 < 32) { load_tile(ti + 1); CP_WAIT(1); }
        else CP_WAIT(0);
        __syncthreads();
        int st = ti & 1;
        uint32_t kd = k2s + st * K2STG;
        uint32_t vd = vts + st * VTSTG;

        // ---- QK: s[8][4] over 12 k16 chunks ----
        float s[8][4];
#pragma unroll
        for (int nf = 0; nf < 8; nf++)
#pragma unroll
            for (int l = 0; l < 4; l++) s[nf][l] = 0.f;
#pragma unroll
        for (int kc = 0; kc < 12; kc++) {
            uint32_t bq[8][2];
#pragma unroll
            for (int np = 0; np < 4; np++)
                ldsm_x4(bq[2*np][0], bq[2*np][1], bq[2*np+1][0], bq[2*np+1][1],
                        kd + ((np*16 + brow) * LDSA + kc*16 + bcol8) * 2);
#pragma unroll
            for (int nf = 0; nf < 8; nf++)
                mma16816(s[nf], aq[kc], bq[nf]);
        }

        // ---- online softmax (rows r0=lane>>2, r1=r0+8) ----
        float rm0 = -CUDART_INF_F, rm1 = -CUDART_INF_F;
#pragma unroll
        for (int nf = 0; nf < 8; nf++) {
            rm0 = fmaxf(rm0, fmaxf(s[nf][0], s[nf][1]));
            rm1 = fmaxf(rm1, fmaxf(s[nf][2], s[nf][3]));
        }
        rm0 = fmaxf(rm0, __shfl_xor_sync(0xffffffffu, rm0, 1));
        rm0 = fmaxf(rm0, __shfl_xor_sync(0xffffffffu, rm0, 2));
        rm1 = fmaxf(rm1, __shfl_xor_sync(0xffffffffu, rm1, 1));
        rm1 = fmaxf(rm1, __shfl_xor_sync(0xffffffffu, rm1, 2));
        float mn0 = fmaxf(m0, rm0), mn1 = fmaxf(m1, rm1);
        float sc0 = __expf(m0 - mn0), sc1 = __expf(m1 - mn1);
        m0 = mn0; m1 = mn1;
        float rs0 = 0.f, rs1 = 0.f;
#pragma unroll
        for (int nf = 0; nf < 8; nf++) {
            s[nf][0] = __expf(s[nf][0] - mn0);
            s[nf][1] = __expf(s[nf][1] - mn0);
            s[nf][2] = __expf(s[nf][2] - mn1);
            s[nf][3] = __expf(s[nf][3] - mn1);
            rs0 += s[nf][0] + s[nf][1];
            rs1 += s[nf][2] + s[nf][3];
        }
        rs0 += __shfl_xor_sync(0xffffffffu, rs0, 1);
        rs0 += __shfl_xor_sync(0xffffffffu, rs0, 2);
        rs1 += __shfl_xor_sync(0xffffffffu, rs1, 1);
        rs1 += __shfl_xor_sync(0xffffffffu, rs1, 2);
        l0 = l0 * sc0 + rs0;
        l1 = l1 * sc1 + rs1;
#pragma unroll
        for (int nf = 0; nf < 8; nf++) {
            o_acc[nf][0] *= sc0; o_acc[nf][1] *= sc0;
            o_acc[nf][2] *= sc1; o_acc[nf][3] *= sc1;
        }

        // ---- pack P into A-frags: Phi / Plo for 4 k16 chunks ----
        uint32_t Ahi[4][4], Alo[4][4];
#pragma unroll
        for (int kc = 0; kc < 4; kc++) {
            int f0 = 2*kc, f1 = 2*kc + 1;
            float h00 = bfr(s[f0][0]), h01 = bfr(s[f0][1]);
            float h02 = bfr(s[f0][2]), h03 = bfr(s[f0][3]);
            float h10 = bfr(s[f1][0]), h11 = bfr(s[f1][1]);
            float h12 = bfr(s[f1][2]), h13 = bfr(s[f1][3]);
            Ahi[kc][0] = pkbf(h00, h01);
            Ahi[kc][1] = pkbf(h02, h03);
            Ahi[kc][2] = pkbf(h10, h11);
            Ahi[kc][3] = pkbf(h12, h13);
            Alo[kc][0] = pkbf(s[f0][0]-h00, s[f0][1]-h01);
            Alo[kc][1] = pkbf(s[f0][2]-h02, s[f0][3]-h03);
            Alo[kc][2] = pkbf(s[f1][0]-h10, s[f1][1]-h11);
            Alo[kc][3] = pkbf(s[f1][2]-h12, s[f1][3]-h13);
        }

        // ---- PV: o += Phi*Vhi + Phi*Vlo + Plo*Vhi ----
#pragma unroll
        for (int kc = 0; kc < 4; kc++) {
            uint32_t bvh[8][2], bvl[8][2];
#pragma unroll
            for (int np = 0; np < 4; np++) {
                ldsm_x4(bvh[2*np][0], bvh[2*np][1], bvh[2*np+1][0], bvh[2*np+1][1],
                        vd + ((np*16 + brow) * LDV + kc*16 + bcol8) * 2);
                ldsm_x4(bvl[2*np][0], bvl[2*np][1], bvl[2*np+1][0], bvl[2*np+1][1],
                        vd + ((64 + np*16 + brow) * LDV + kc*16 + bcol8) * 2);
            }
#pragma unroll
            for (int nf = 0; nf < 8; nf++) {
                mma16816(o_acc[nf], Ahi[kc], bvh[nf]);
                mma16816(o_acc[nf], Ahi[kc], bvl[nf]);
                mma16816(o_acc[nf], Alo[kc], bvh[nf]);
            }
        }
        __syncthreads();
    }

    // ---- epilogue: write (b,t,d) fp32 ----
    float inv0 = 1.0f / l0, inv1 = 1.0f / l1;
    int r0 = q0 + wid * 16 + (lane >> 2);
    int r1 = r0 + 8;
#pragma unroll
    for (int nf = 0; nf < 8; nf++) {
        int d = nf * 8 + 2 * (lane & 3);
        *(float2*)(g_o + (size_t)(b * Tc + r0) * Dc + h * HDc + d) =
            make_float2(o_acc[nf][0] * inv0, o_acc[nf][1] * inv0);
        *(float2*)(g_o + (size_t)(b * Tc + r1) * Dc + h * HDc + d) =
            make_float2(o_acc[nf][2] * inv1, o_acc[nf][3] * inv1);
    }
}

// ---------------------------------------------------------------------------
extern "C" void kernel_launch(void* const* d_in, const int* in_sizes, int n_in,
                              void* d_out, int out_size) {
    const float* x   = (const float*)d_in[0];
    const float* Wq  = (const float*)d_in[1];
    const float* bq  = (const float*)d_in[2];
    const float* Wk  = (const float*)d_in[3];
    const float* bk  = (const float*)d_in[4];
    const float* Wv  = (const float*)d_in[5];
    const float* bv  = (const float*)d_in[6];
    const float* Wo  = (const float*)d_in[7];
    const float* bo  = (const float*)d_in[8];
    const float* A   = (const float*)d_in[9];
    const float* ll  = (const float*)d_in[10];
    float* out = (float*)d_out;

    cudaFuncSetAttribute(gemm_tc, cudaFuncAttributeMaxDynamicSharedMemorySize, SMEM_DYN);
    cudaFuncSetAttribute(attn_tc, cudaFuncAttributeMaxDynamicSharedMemorySize, ASMEM);

    __nv_bfloat16 *x2, *w2q, *w2k, *w2v, *w2o, *o2;
    float* o_ptr;
    cudaGetSymbolAddress((void**)&x2,  g_x2);
    cudaGetSymbolAddress((void**)&w2q, g_w2);
    cudaGetSymbolAddress((void**)&o2,  g_o2);
    cudaGetSymbolAddress((void**)&o_ptr, g_o);
    w2k = w2q + (size_t)Dc*KTOT; w2v = w2k + (size_t)Dc*KTOT; w2o = w2v + (size_t)Dc*KTOT;

    const float* Ws[4] = {Wq, Wk, Wv, Wo};
    __nv_bfloat16* W2s[4] = {w2q, w2k, w2v, w2o};

    split_kernel<<<(Mc*Dc/2 + 255)/256, 256>>>(x, x2, Mc, 0);
    for (int i = 0; i < 4; i++)
        split_kernel<<<(Dc*Dc/2 + 255)/256, 256>>>(Ws[i], W2s[i], Dc, 1);

    dim3 ggrid(Mc / BM, Dc / BN);   // (32, 8)
    gemm_tc<<<ggrid, 256, SMEM_DYN>>>(x2, w2q, bq, nullptr, 0);  // q  -> fp32
    gemm_tc<<<ggrid, 256, SMEM_DYN>>>(x2, w2k, bk, nullptr, 1);  // k  -> g_k2 triple
    gemm_tc<<<ggrid, 256, SMEM_DYN>>>(x2, w2v, bv, nullptr, 2);  // v  -> g_v2t planes

    gdiag_kernel<<<4, 256>>>(A, ll);
    ksum2_kernel<<<Bc*Hc, 256>>>();
    sgprep_kernel<<<(Bc*Hc*Tc*HDc + 255)/256, 256>>>();

    attn_tc<<<dim3(Tc / AT_M, Bc * Hc), 256, ASMEM>>>();

    split_kernel<<<(Mc*Dc/2 + 255)/256, 256>>>(o_ptr, o2, Mc, 0);
    gemm_tc<<<ggrid, 256, SMEM_DYN>>>(o2, w2o, bo, out, 3);      // out projection
}